// round 10
// baseline (speedup 1.0000x reference)
#include <cuda_runtime.h>
#include <math.h>

#define BB 16
#define TT 1024
#define DDIM 512
#define BT (BB*TT)
#define PER ((long)BT*DDIM)

__device__ float g_scratch[13L*PER + 16777216L + 2L*262144L];
__device__ float g_prev[2][BB*DDIM];
__device__ int   g_cnt[TT + 1];

__device__ __forceinline__ float sigf(float x) { return 1.f / (1.f + expf(-x)); }
__device__ __forceinline__ int ldacq(const int* p) {
    int v; asm volatile("ld.acquire.gpu.global.b32 %0, [%1];" : "=r"(v) : "l"(p) : "memory");
    return v;
}
__device__ __forceinline__ void redrel(int* p) {
    asm volatile("red.release.gpu.global.add.s32 [%0], 1;" :: "l"(p) : "memory");
}
__device__ __forceinline__ void cp16(unsigned saddr, const void* g) {
    asm volatile("cp.async.ca.shared.global [%0], [%1], 16;" :: "r"(saddr), "l"(g));
}

__global__ void init_k() {
    int tid = blockIdx.x * blockDim.x + threadIdx.x;
    if (tid < BB*DDIM) g_prev[0][tid] = 0.f;
    if (tid < TT + 1)  g_cnt[tid] = 0;
}

// in [Z,R,C] -> out [Z,C,R]
__global__ void transpose_k(const float* __restrict__ in, float* __restrict__ out,
                            int R, int C, long sIn, long sOut) {
    __shared__ float tile[32][33];
    const float* ib = in  + (long)blockIdx.z * sIn;
    float*       ob = out + (long)blockIdx.z * sOut;
    int c0 = blockIdx.x * 32, r0 = blockIdx.y * 32;
    for (int i = threadIdx.y; i < 32; i += 8)
        tile[i][threadIdx.x] = ib[(long)(r0 + i) * C + c0 + threadIdx.x];
    __syncthreads();
    for (int i = threadIdx.y; i < 32; i += 8)
        ob[(long)(c0 + i) * R + r0 + threadIdx.x] = tile[threadIdx.x][i];
}

__global__ void softmax1024(float* __restrict__ data) {
    __shared__ float red[8];
    int tid = threadIdx.x;
    float4* p = ((float4*)data) + ((long)blockIdx.x << 8);
    float4 v = p[tid];
    float m = fmaxf(fmaxf(v.x, v.y), fmaxf(v.z, v.w));
    #pragma unroll
    for (int o = 16; o; o >>= 1) m = fmaxf(m, __shfl_xor_sync(0xffffffffu, m, o));
    if ((tid & 31) == 0) red[tid >> 5] = m;
    __syncthreads();
    m = red[0];
    #pragma unroll
    for (int i = 1; i < 8; i++) m = fmaxf(m, red[i]);
    v.x = __expf(v.x - m); v.y = __expf(v.y - m);
    v.z = __expf(v.z - m); v.w = __expf(v.w - m);
    float s = v.x + v.y + v.z + v.w;
    #pragma unroll
    for (int o = 16; o; o >>= 1) s += __shfl_xor_sync(0xffffffffu, s, o);
    __syncthreads();
    if ((tid & 31) == 0) red[tid >> 5] = s;
    __syncthreads();
    s = red[0];
    #pragma unroll
    for (int i = 1; i < 8; i++) s += red[i];
    float inv = 1.f / s;
    v.x *= inv; v.y *= inv; v.z *= inv; v.w *= inv;
    p[tid] = v;
}

// ---------------------------------------------------------------------------
// tf32 tensor-core NT GEMM, cp.async 3-stage pipeline.
// smem tiles row-major [128 m][16 k] with stride 20 floats: fragment LDS
// conflict-free (bank = (20g+t) mod 32 covers all 32), cp.async writes 16B
// chunks straight (no transpose, no cvt — HW tf32 truncation).
// EPI: 0 none 1 silu 2 sigmoid 3 sig(x)*aux1 4 silu(x+aux1) 5 lerp(aux2,aux1,sig)
// ---------------------------------------------------------------------------
#define TSTRIDE 20
#define TSLOT (128 * TSTRIDE)          // floats per tile slot
#define GSMEM (6 * TSLOT * 4)          // 61440 bytes

template<int EPI>
__global__ __launch_bounds__(256)
void tgemm(const float* __restrict__ A, const float* __restrict__ Bw,
           const float* __restrict__ bias,
           const float* __restrict__ aux1, const float* __restrict__ aux2,
           float* __restrict__ C,
           int K, int ldb, int N, long sA, long sB, long sC, float scale)
{
    extern __shared__ float smem[];
    float* AsBase = smem;               // 3 slots
    float* BsBase = smem + 3 * TSLOT;   // 3 slots
    const int tid  = threadIdx.x;
    const int lane = tid & 31, warp = tid >> 5;
    const int wm = warp >> 2, wn = warp & 3;
    const int g = lane >> 2, t = lane & 3;
    const float* Ab = A  + (long)blockIdx.z * sA + (long)blockIdx.y * 128 * K;
    const float* Bb = Bw + (long)blockIdx.z * sB + (long)blockIdx.x * 128 * ldb;
    const int lr = tid >> 2, lc = (tid & 3) << 2;   // loader: row, k-offset (16B)

    float acc[4][4][4];
    #pragma unroll
    for (int i = 0; i < 4; i++)
        #pragma unroll
        for (int j = 0; j < 4; j++)
            #pragma unroll
            for (int q = 0; q < 4; q++) acc[i][j][q] = 0.f;

    auto ISSUE = [&](int s, int kt) {
        float* As = AsBase + s * TSLOT;
        float* Bs = BsBase + s * TSLOT;
        cp16((unsigned)__cvta_generic_to_shared(&As[lr * TSTRIDE + lc]),
             &Ab[(long)lr * K + kt + lc]);
        cp16((unsigned)__cvta_generic_to_shared(&As[(lr + 64) * TSTRIDE + lc]),
             &Ab[(long)(lr + 64) * K + kt + lc]);
        cp16((unsigned)__cvta_generic_to_shared(&Bs[lr * TSTRIDE + lc]),
             &Bb[(long)lr * ldb + kt + lc]);
        cp16((unsigned)__cvta_generic_to_shared(&Bs[(lr + 64) * TSTRIDE + lc]),
             &Bb[(long)(lr + 64) * ldb + kt + lc]);
        asm volatile("cp.async.commit_group;" ::: "memory");
    };

    auto MM = [&](int s) {
        const float* As = AsBase + s * TSLOT;
        const float* Bs = BsBase + s * TSLOT;
        #pragma unroll
        for (int c = 0; c < 2; c++) {
            const int k0 = c * 8 + t;
            unsigned af[4][4], bf[4][2];
            #pragma unroll
            for (int i = 0; i < 4; i++) {
                const int m = wm * 64 + i * 16 + g;
                af[i][0] = __float_as_uint(As[m * TSTRIDE + k0]);
                af[i][1] = __float_as_uint(As[(m + 8) * TSTRIDE + k0]);
                af[i][2] = __float_as_uint(As[m * TSTRIDE + k0 + 4]);
                af[i][3] = __float_as_uint(As[(m + 8) * TSTRIDE + k0 + 4]);
            }
            #pragma unroll
            for (int j = 0; j < 4; j++) {
                const int n = wn * 32 + j * 8 + g;
                bf[j][0] = __float_as_uint(Bs[n * TSTRIDE + k0]);
                bf[j][1] = __float_as_uint(Bs[n * TSTRIDE + k0 + 4]);
            }
            #pragma unroll
            for (int i = 0; i < 4; i++)
                #pragma unroll
                for (int j = 0; j < 4; j++)
                    asm volatile(
                        "mma.sync.aligned.m16n8k8.row.col.f32.tf32.tf32.f32 "
                        "{%0,%1,%2,%3}, {%4,%5,%6,%7}, {%8,%9}, {%0,%1,%2,%3};\n"
                        : "+f"(acc[i][j][0]), "+f"(acc[i][j][1]),
                          "+f"(acc[i][j][2]), "+f"(acc[i][j][3])
                        : "r"(af[i][0]), "r"(af[i][1]), "r"(af[i][2]), "r"(af[i][3]),
                          "r"(bf[j][0]), "r"(bf[j][1]));
        }
    };

    const int nt = K >> 4;
    ISSUE(0, 0);
    ISSUE(1, 16);
    for (int tt = 0; tt < nt; tt++) {
        if (tt < nt - 1)
            asm volatile("cp.async.wait_group 1;" ::: "memory");
        else
            asm volatile("cp.async.wait_group 0;" ::: "memory");
        __syncthreads();
        MM(tt % 3);
        if (tt + 2 < nt) ISSUE((tt + 2) % 3, (tt + 2) * 16);
    }

    const int gn_base = blockIdx.x * 128 + wn * 32;
    #pragma unroll
    for (int i = 0; i < 4; i++) {
        const long m = (long)blockIdx.y * 128 + wm * 64 + i * 16 + g;
        #pragma unroll
        for (int j = 0; j < 4; j++) {
            const int n0 = gn_base + j * 8 + 2 * t;
            const float b0 = bias ? bias[n0]     : 0.f;
            const float b1 = bias ? bias[n0 + 1] : 0.f;
            const long i0 = (long)blockIdx.z * sC + m * N + n0;
            const long i2 = i0 + 8L * N;
            float x[4] = { acc[i][j][0] * scale + b0, acc[i][j][1] * scale + b1,
                           acc[i][j][2] * scale + b0, acc[i][j][3] * scale + b1 };
            const long idx[4] = { i0, i0 + 1, i2, i2 + 1 };
            float o[4];
            #pragma unroll
            for (int q = 0; q < 4; q++) {
                float xv = x[q];
                if (EPI == 0)      o[q] = xv;
                else if (EPI == 1) o[q] = xv * sigf(xv);
                else if (EPI == 2) o[q] = sigf(xv);
                else if (EPI == 3) o[q] = sigf(xv) * aux1[idx[q]];
                else if (EPI == 4) { float y = xv + aux1[idx[q]]; o[q] = y * sigf(y); }
                else { float s_ = sigf(xv); o[q] = s_ * aux1[idx[q]] + (1.f - s_) * aux2[idx[q]]; }
            }
            float2 w0 = { o[0], o[1] }, w1 = { o[2], o[3] };
            *(float2*)&C[i0] = w0;
            *(float2*)&C[i2] = w1;
        }
    }
}

// ---------------------------------------------------------------------------
// EMA recurrence: 128 persistent CTAs x 256 thr. Warp w owns batches {2w,2w+1}
// and ALL 8 rows (4 Wa + 4 Wd) — weights in 128 regs, state read directly
// from L2 (__ldcv, coalesced), no smem staging, 2 bars/step.
// ---------------------------------------------------------------------------
__global__ __launch_bounds__(256, 1)
void ema_rec(const float* __restrict__ bin, const float* __restrict__ pa,
             const float* __restrict__ pd, const float* __restrict__ Wa,
             const float* __restrict__ Wd, float* __restrict__ ema)
{
    __shared__ float dot_s[8 * 16];
    const int tid  = threadIdx.x;
    const int lane = tid & 31, warp = tid >> 5;
    const int j0 = blockIdx.x * 4;
    const int b0 = warp * 2;
    const int er = tid >> 4, eb = tid & 15;

    float wreg[8][16];
    #pragma unroll
    for (int r = 0; r < 4; r++)
        #pragma unroll
        for (int dd = 0; dd < 16; dd++) {
            wreg[r][dd]     = Wa[(long)(j0 + r) * 1024 + (dd << 5) + lane];
            wreg[4 + r][dd] = Wd[(long)(j0 + r) * 1024 + (dd << 5) + lane];
        }

    for (int t = 0; t < TT; t++) {
        float bt_v = 0.f, pa_v = 0.f, pd_v = 0.f;
        if (tid < 64) {
            long off = ((long)eb * TT + t) * DDIM + j0 + er;
            bt_v = bin[off]; pa_v = pa[off]; pd_v = pd[off];
        }
        if (t) {
            if (lane == 0) {
                while (ldacq(&g_cnt[t]) < 128) { __nanosleep(32); }
            }
            __syncwarp();
        }
        const float* pg = g_prev[t & 1];
        float pv0[16], pv1[16];
        #pragma unroll
        for (int dd = 0; dd < 16; dd++)
            pv0[dd] = __ldcv(pg + (long)b0 * 512 + (dd << 5) + lane);
        #pragma unroll
        for (int dd = 0; dd < 16; dd++)
            pv1[dd] = __ldcv(pg + (long)(b0 + 1) * 512 + (dd << 5) + lane);
        float pcur = 0.f;
        if (tid < 64) pcur = __ldcv(pg + (long)eb * 512 + j0 + er);

        float acc[8][2];
        #pragma unroll
        for (int r = 0; r < 8; r++) { acc[r][0] = 0.f; acc[r][1] = 0.f; }

        #pragma unroll
        for (int dd = 0; dd < 16; dd++) {
            const float p0 = pv0[dd], p1 = pv1[dd];
            #pragma unroll
            for (int r = 0; r < 8; r++) {
                acc[r][0] += wreg[r][dd] * p0;
                acc[r][1] += wreg[r][dd] * p1;
            }
        }
        #pragma unroll
        for (int r = 0; r < 8; r++)
            #pragma unroll
            for (int bI = 0; bI < 2; bI++) {
                float v = acc[r][bI];
                #pragma unroll
                for (int o = 16; o; o >>= 1) v += __shfl_xor_sync(0xffffffffu, v, o);
                acc[r][bI] = v;
            }
        if (lane == 0) {
            #pragma unroll
            for (int r = 0; r < 8; r++) {
                dot_s[r * 16 + b0]     = acc[r][0];
                dot_s[r * 16 + b0 + 1] = acc[r][1];
            }
        }
        __syncthreads();

        if (tid < 64) {
            float alpha = tanhf(dot_s[er * 16 + eb] + pa_v);
            float delta = tanhf(dot_s[(4 + er) * 16 + eb] + pd_v);
            float x = alpha * bt_v + (1.f - alpha * delta) * pcur;
            float e = 1.f / (1.f + expf(-x));
            g_prev[(t + 1) & 1][eb * 512 + j0 + er] = e;
            ema[((long)eb * TT + t) * DDIM + j0 + er] = e;
        }
        __syncthreads();
        if (tid == 0) redrel(&g_cnt[t + 1]);
    }
}

extern "C" void kernel_launch(void* const* d_in, const int* in_sizes, int n_in,
                              void* d_out, int out_size) {
    const float* b    = (const float*)d_in[0];
    const float* Wq   = (const float*)d_in[1];
    const float* bq   = (const float*)d_in[2];
    const float* Wk   = (const float*)d_in[3];
    const float* bk   = (const float*)d_in[4];
    const float* Wv   = (const float*)d_in[5];
    const float* bv   = (const float*)d_in[6];
    const float* Wa   = (const float*)d_in[7];
    const float* ba   = (const float*)d_in[8];
    const float* Wd   = (const float*)d_in[9];
    const float* bd   = (const float*)d_in[10];
    const float* Wout = (const float*)d_in[11];
    const float* bout = (const float*)d_in[12];
    const float* W_f  = (const float*)d_in[13];
    const float* b_f  = (const float*)d_in[14];
    const float* W_ec = (const float*)d_in[15];
    const float* W_zc = (const float*)d_in[16];
    const float* b_C  = (const float*)d_in[17];
    const float* W_i  = (const float*)d_in[18];
    const float* b_i  = (const float*)d_in[19];
    const float* W_o  = (const float*)d_in[20];
    const float* b_o  = (const float*)d_in[21];
    float* out = (float*)d_out;

    float* S = nullptr;
    cudaGetSymbolAddress((void**)&S, g_scratch);
    float* pre_a  = S + 0 * PER;
    float* pre_d  = S + 1 * PER;
    float* ema    = S + 2 * PER;
    float* bema   = S + 3 * PER;
    float* q      = S + 4 * PER;
    float* kmat   = S + 5 * PER;
    float* v      = S + 6 * PER;
    float* vT     = S + 7 * PER;
    float* z      = S + 8 * PER;
    float* zf     = S + 9 * PER;
    float* tmpc   = S + 10 * PER;
    float* zc     = S + 11 * PER;
    float* bh     = S + 12 * PER;
    float* scores = S + 13 * PER;
    float* wT1    = scores + 16777216L;
    float* wT2    = wT1 + 262144L;

    cudaFuncSetAttribute(tgemm<0>, cudaFuncAttributeMaxDynamicSharedMemorySize, GSMEM);
    cudaFuncSetAttribute(tgemm<1>, cudaFuncAttributeMaxDynamicSharedMemorySize, GSMEM);
    cudaFuncSetAttribute(tgemm<2>, cudaFuncAttributeMaxDynamicSharedMemorySize, GSMEM);
    cudaFuncSetAttribute(tgemm<3>, cudaFuncAttributeMaxDynamicSharedMemorySize, GSMEM);
    cudaFuncSetAttribute(tgemm<4>, cudaFuncAttributeMaxDynamicSharedMemorySize, GSMEM);
    cudaFuncSetAttribute(tgemm<5>, cudaFuncAttributeMaxDynamicSharedMemorySize, GSMEM);

    const dim3 blk(256);
    const dim3 gD(4, 128, 1);
    const long sBT = (long)TT * DDIM;
    const long sTT = (long)TT * TT;
    const float iscale = 1.f / sqrtf(512.f);

    init_k<<<32, 256>>>();
    transpose_k<<<dim3(16, 16, 1), dim3(32, 8)>>>(W_ec, wT1, 512, 512, 0, 0);
    transpose_k<<<dim3(16, 16, 1), dim3(32, 8)>>>(W_zc, wT2, 512, 512, 0, 0);

    tgemm<0><<<gD, blk, GSMEM>>>(b, Wa + 512, ba, nullptr, nullptr, pre_a, 512, 1024, 512, 0, 0, 0, 1.f);
    tgemm<0><<<gD, blk, GSMEM>>>(b, Wd + 512, bd, nullptr, nullptr, pre_d, 512, 1024, 512, 0, 0, 0, 1.f);

    ema_rec<<<128, 256>>>(b, pre_a, pre_d, Wa, Wd, ema);

    tgemm<1><<<gD, blk, GSMEM>>>(ema, Wout, bout, nullptr, nullptr, bema, 512, 512, 512, 0, 0, 0, 1.f);

    tgemm<0><<<gD, blk, GSMEM>>>(bema, Wq, bq, nullptr, nullptr, q,    512, 512, 512, 0, 0, 0, 1.f);
    tgemm<0><<<gD, blk, GSMEM>>>(bema, Wk, bk, nullptr, nullptr, kmat, 512, 512, 512, 0, 0, 0, 1.f);
    tgemm<0><<<gD, blk, GSMEM>>>(bema, Wv, bv, nullptr, nullptr, v,    512, 512, 512, 0, 0, 0, 1.f);

    tgemm<0><<<dim3(8, 8, 16), blk, GSMEM>>>(q, kmat, nullptr, nullptr, nullptr, scores,
                                             512, 512, 1024, sBT, sBT, sTT, iscale);
    softmax1024<<<BT, 256>>>(scores);

    transpose_k<<<dim3(16, 32, 16), dim3(32, 8)>>>(v, vT, 1024, 512, sBT, sBT);

    tgemm<0><<<dim3(4, 8, 16), blk, GSMEM>>>(scores, vT, nullptr, nullptr, nullptr, z,
                                             1024, 1024, 512, sTT, sBT, sBT, 1.f);

    tgemm<3><<<gD, blk, GSMEM>>>(bema, W_f, b_f, z, nullptr, zf, 512, 512, 512, 0, 0, 0, 1.f);
    tgemm<0><<<gD, blk, GSMEM>>>(bema, wT1, nullptr, nullptr, nullptr, tmpc, 512, 512, 512, 0, 0, 0, 1.f);
    tgemm<4><<<gD, blk, GSMEM>>>(zf, wT2, b_C, tmpc, nullptr, zc, 512, 512, 512, 0, 0, 0, 1.f);
    tgemm<5><<<gD, blk, GSMEM>>>(bema, W_i, b_i, zc, b, bh, 512, 512, 512, 0, 0, 0, 1.f);
    tgemm<2><<<gD, blk, GSMEM>>>(bh, W_o, b_o, nullptr, nullptr, out, 512, 512, 512, 0, 0, 0, 1.f);
}